// round 6
// baseline (speedup 1.0000x reference)
#include <cuda_runtime.h>
#include <math.h>

// OHNM loss: pos_sum of BCE over target>0, plus top-k (k = 3*pos) softplus sum
// over negatives, selected by a value threshold found via sample-bracketed
// two-level histogram selection. softplus is monotone, so top-k sum == sum
// over {x > threshold} (+ residual at the boundary bin).

#define COARSE_BINS 2048
#define NB          1536      // fine bins covering 3 coarse bins; 3<<21 / 1536 = 2^12
#define FINE_SHIFT  12
#define SAMP_BLOCKS 64
#define SAMP_THREADS 1024
#define MAIN_BLOCKS 444
#define MAIN_THREADS 512

__device__ unsigned int g_coarse[COARSE_BINS];
__device__ unsigned int g_fine[NB];
__device__ unsigned int g_key_base;
__device__ unsigned int g_key_hi;
__device__ float        g_pos_sum;
__device__ float        g_sum_above;
__device__ unsigned int g_count_above;

// order-preserving float->uint key (larger float => larger key)
__device__ __forceinline__ unsigned int mono_key(float x) {
    unsigned int u = __float_as_uint(x);
    return (u & 0x80000000u) ? ~u : (u | 0x80000000u);
}
__device__ __forceinline__ float key_to_float(unsigned int key) {
    unsigned int u = (key & 0x80000000u) ? (key & 0x7fffffffu) : ~key;
    return __uint_as_float(u);
}
// BCE with logits, label 0  == softplus(x)
__device__ __forceinline__ float softplus_pos(float x) {
    return fmaxf(x, 0.0f) + log1pf(expf(-fabsf(x)));
}
// general stable BCE with logits
__device__ __forceinline__ float bce_wl(float x, float y) {
    return fmaxf(x, 0.0f) - x * y + log1pf(expf(-fabsf(x)));
}

// ---------------------------------------------------------------- k_init ----
__global__ void k_init() {
    int t = threadIdx.x;
    for (int i = t; i < COARSE_BINS; i += blockDim.x) g_coarse[i] = 0u;
    for (int i = t; i < NB; i += blockDim.x) g_fine[i] = 0u;
    if (t == 0) { g_pos_sum = 0.0f; g_sum_above = 0.0f; g_count_above = 0u; }
}

// -------------------------------------------------------------- k_sample ----
// 64 chunks x 1024 contiguous samples => coalesced ~1MB read, 2048-bin
// histogram of top-11 key bits over sampled negatives.
__global__ void __launch_bounds__(SAMP_THREADS) k_sample(
    const float* __restrict__ x, const float* __restrict__ y, int n)
{
    __shared__ unsigned int sh[COARSE_BINS];
    for (int i = threadIdx.x; i < COARSE_BINS; i += blockDim.x) sh[i] = 0u;
    __syncthreads();

    long long stride = (long long)n / SAMP_BLOCKS;
    long long idx = (long long)blockIdx.x * stride + threadIdx.x;
    if (idx < n) {
        float yv = __ldg(&y[idx]);
        if (yv == 0.0f) {
            unsigned int key = mono_key(__ldg(&x[idx]));
            atomicAdd(&sh[key >> 21], 1u);
        }
    }
    __syncthreads();
    for (int i = threadIdx.x; i < COARSE_BINS; i += blockDim.x) {
        unsigned int v = sh[i];
        if (v) atomicAdd(&g_coarse[i], v);
    }
}

// ------------------------------------------------------------- k_bracket ----
// Single block: suffix-scan sample histogram, find the coarse bin where the
// scaled suffix count crosses k, emit a 3-bin bracket [key_base, key_hi).
__global__ void __launch_bounds__(512) k_bracket(const int* pos_ptr, int n) {
    __shared__ unsigned int suf[COARSE_BINS];
    __shared__ unsigned int part[512];
    __shared__ int s_bb;
    int t = threadIdx.x;

    unsigned int s = 0;
#pragma unroll
    for (int j = 3; j >= 0; --j) {
        s += g_coarse[4 * t + j];
        suf[4 * t + j] = s;
    }
    part[t] = s;
    if (t == 0) s_bb = 1;
    __syncthreads();
    for (int off = 1; off < 512; off <<= 1) {
        unsigned int v = (t + off < 512) ? part[t + off] : 0u;
        __syncthreads();
        part[t] += v;
        __syncthreads();
    }
    unsigned int excl = part[t] - s;  // sum of all bins above this thread's group
#pragma unroll
    for (int j = 0; j < 4; ++j) suf[4 * t + j] += excl;
    __syncthreads();

    int pos = pos_ptr ? *pos_ptr : 200000;
    unsigned long long k = (unsigned long long)pos * 3ull;
    unsigned long long scale = (unsigned long long)(n / (SAMP_BLOCKS * SAMP_THREADS));
    if (scale < 1ull) scale = 1ull;

#pragma unroll
    for (int j = 0; j < 4; ++j) {
        int b = 4 * t + j;
        bool c  = (unsigned long long)suf[b] * scale >= k;
        bool cn = (b + 1 < COARSE_BINS) &&
                  ((unsigned long long)suf[b + 1] * scale >= k);
        if (c && !cn) atomicMax(&s_bb, b);
    }
    __syncthreads();
    if (t == 0) {
        int bb = s_bb;
        if (bb < 1) bb = 1;
        if (bb > COARSE_BINS - 3) bb = COARSE_BINS - 3;
        g_key_base = (unsigned int)(bb - 1) << 21;
        g_key_hi   = (unsigned int)(bb + 2) << 21;   // bb+2 <= 2047, no overflow
    }
}

// ---------------------------------------------------------------- k_main ----
// The one full 67MB pass: pos BCE sum, exact softplus sum above the bracket,
// and a 1536-bin count histogram for bracket elements only.
__global__ void __launch_bounds__(MAIN_THREADS) k_main(
    const float* __restrict__ x, const float* __restrict__ y, int n)
{
    __shared__ unsigned int sh[NB];
    __shared__ float sw_pos[16];
    __shared__ float sw_sa[16];
    __shared__ unsigned int sw_ca[16];
    for (int i = threadIdx.x; i < NB; i += blockDim.x) sh[i] = 0u;
    __syncthreads();

    const unsigned int key_base = g_key_base;
    const unsigned int key_hi   = g_key_hi;

    float pos_l = 0.0f, sa_l = 0.0f;
    unsigned int ca_l = 0u;

    const int nv4 = n >> 2;
    const float4* __restrict__ x4 = (const float4*)x;
    const float4* __restrict__ y4 = (const float4*)y;
    int tid = blockIdx.x * blockDim.x + threadIdx.x;
    int stride = gridDim.x * blockDim.x;

    for (int i = tid; i < nv4; i += stride) {
        float4 xv = __ldg(&x4[i]);
        float4 yv = __ldg(&y4[i]);
        float xs[4] = {xv.x, xv.y, xv.z, xv.w};
        float ys[4] = {yv.x, yv.y, yv.z, yv.w};
#pragma unroll
        for (int j = 0; j < 4; ++j) {
            float xx = xs[j], yy = ys[j];
            if (yy > 0.0f) {
                pos_l += bce_wl(xx, yy);
            } else {
                unsigned int key = mono_key(xx);
                if (key >= key_hi) {
                    sa_l += softplus_pos(xx);
                    ca_l++;
                } else if (key >= key_base) {
                    atomicAdd(&sh[(key - key_base) >> FINE_SHIFT], 1u);
                }
            }
        }
    }
    // scalar tail (n is a multiple of 4 for this problem, but be safe)
    if (tid == 0) {
        for (int i = nv4 << 2; i < n; ++i) {
            float xx = x[i], yy = y[i];
            if (yy > 0.0f) pos_l += bce_wl(xx, yy);
            else {
                unsigned int key = mono_key(xx);
                if (key >= key_hi) { sa_l += softplus_pos(xx); ca_l++; }
                else if (key >= key_base)
                    atomicAdd(&sh[(key - key_base) >> FINE_SHIFT], 1u);
            }
        }
    }

    // block reduce the three scalars
#pragma unroll
    for (int off = 16; off; off >>= 1) {
        pos_l += __shfl_down_sync(0xffffffffu, pos_l, off);
        sa_l  += __shfl_down_sync(0xffffffffu, sa_l, off);
        ca_l  += __shfl_down_sync(0xffffffffu, ca_l, off);
    }
    int wid = threadIdx.x >> 5, lid = threadIdx.x & 31;
    if (lid == 0) { sw_pos[wid] = pos_l; sw_sa[wid] = sa_l; sw_ca[wid] = ca_l; }
    __syncthreads();   // also orders all sh[] atomics before the merge below
    if (threadIdx.x == 0) {
        float p = 0.0f, sA = 0.0f; unsigned int cA = 0u;
        int nw = blockDim.x >> 5;
        for (int w = 0; w < nw; ++w) { p += sw_pos[w]; sA += sw_sa[w]; cA += sw_ca[w]; }
        atomicAdd(&g_pos_sum, p);
        atomicAdd(&g_sum_above, sA);
        atomicAdd(&g_count_above, cA);
    }
    for (int i = threadIdx.x; i < NB; i += blockDim.x) {
        unsigned int v = sh[i];
        if (v) atomicAdd(&g_fine[i], v);
    }
}

// --------------------------------------------------------------- k_final ----
// Single block: suffix-scan fine histogram, find boundary bin for the
// residual r = k - count_above, assemble the loss.
__global__ void __launch_bounds__(512) k_final(const int* pos_ptr, float* out) {
    __shared__ unsigned int suf[NB];
    __shared__ unsigned int part[512];
    __shared__ int s_bstar;
    __shared__ float fw[16];
    int t = threadIdx.x;

    const unsigned int key_base = g_key_base;
    unsigned int cnt[3];
    unsigned int s = 0;
#pragma unroll
    for (int j = 2; j >= 0; --j) {
        cnt[j] = g_fine[3 * t + j];
        s += cnt[j];
        suf[3 * t + j] = s;
    }
    part[t] = s;
    if (t == 0) s_bstar = 0;
    __syncthreads();
    for (int off = 1; off < 512; off <<= 1) {
        unsigned int v = (t + off < 512) ? part[t + off] : 0u;
        __syncthreads();
        part[t] += v;
        __syncthreads();
    }
    unsigned int excl = part[t] - s;
#pragma unroll
    for (int j = 0; j < 3; ++j) suf[3 * t + j] += excl;
    __syncthreads();

    int pos = pos_ptr ? *pos_ptr : 200000;
    long long k = (long long)pos * 3;
    long long r = k - (long long)g_count_above;
    if (r < 0) r = 0;

#pragma unroll
    for (int j = 0; j < 3; ++j) {
        int b = 3 * t + j;
        bool c  = (long long)suf[b] >= r;
        bool cn = (b + 1 < NB) && ((long long)suf[b + 1] >= r);
        if (c && !cn) atomicMax(&s_bstar, b);
    }
    __syncthreads();
    int bstar = s_bstar;

    // weighted softplus sum over bins strictly above the boundary bin
    float wl = 0.0f;
#pragma unroll
    for (int j = 0; j < 3; ++j) {
        int b = 3 * t + j;
        if (b > bstar && cnt[j]) {
            unsigned int kmid = key_base + ((unsigned int)b << FINE_SHIFT)
                              + (1u << (FINE_SHIFT - 1));
            wl += (float)cnt[j] * softplus_pos(key_to_float(kmid));
        }
    }
#pragma unroll
    for (int off = 16; off; off >>= 1)
        wl += __shfl_down_sync(0xffffffffu, wl, off);
    if ((t & 31) == 0) fw[t >> 5] = wl;
    __syncthreads();

    if (t == 0) {
        float wsum = 0.0f;
        for (int w = 0; w < (int)(blockDim.x >> 5); ++w) wsum += fw[w];
        long long taken = (bstar + 1 < NB) ? (long long)suf[bstar + 1] : 0;
        long long resid = r - taken;
        if (resid < 0) resid = 0;
        unsigned int kmid = key_base + ((unsigned int)bstar << FINE_SHIFT)
                          + (1u << (FINE_SHIFT - 1));
        float neg = g_sum_above + wsum +
                    (float)resid * softplus_pos(key_to_float(kmid));
        out[0] = (g_pos_sum + neg) / (float)(pos + k);
    }
}

// ----------------------------------------------------------------------------
extern "C" void kernel_launch(void* const* d_in, const int* in_sizes, int n_in,
                              void* d_out, int out_size) {
    const float* x = (const float*)d_in[0];
    const float* y = (const float*)d_in[1];
    const int* posp = (n_in >= 3) ? (const int*)d_in[2] : nullptr;
    int n = in_sizes[0];

    k_init<<<1, 1024>>>();
    k_sample<<<SAMP_BLOCKS, SAMP_THREADS>>>(x, y, n);
    k_bracket<<<1, 512>>>(posp, n);
    k_main<<<MAIN_BLOCKS, MAIN_THREADS>>>(x, y, n);
    k_final<<<1, 512>>>(posp, (float*)d_out);
    (void)out_size;
}